// round 5
// baseline (speedup 1.0000x reference)
#include <cuda_runtime.h>
#include <stdint.h>

#define BN      16384
#define IN_DIM  256
#define HID     128
#define NCLS    8
#define T_STEPS 64
#define BETA    0.9f

// Scratch (no cudaMalloc allowed)
__device__ float g_cur1[BN * HID];              // 8 MB
__device__ uint4 g_masks[T_STEPS * BN];         // 16 MB  [t][s] spike masks
__device__ float g_W1T[IN_DIM * HID];           // 128 KB
__device__ float4 g_cur2[2][T_STEPS * BN];      // 33.5 MB [half][t][s] layer-2 currents

// ---------------------------------------------------------------------------
// K0: W1T[k][h] = W1[h][k]
// ---------------------------------------------------------------------------
__global__ __launch_bounds__(256) void k0_w1t(const float* __restrict__ W1)
{
    int idx = blockIdx.x * 256 + threadIdx.x;
    int h = idx & (HID - 1);
    int k = idx >> 7;
    g_W1T[k * HID + h] = W1[h * IN_DIM + k];
}

// ---------------------------------------------------------------------------
// K1: cur1 = x @ W1^T + b1.  64s x 128h tile, 256 thr, 8s x 4h per thread.
// ---------------------------------------------------------------------------
#define XS_STRIDE 36

__global__ __launch_bounds__(256) void k1_fc1(const float* __restrict__ x,
                                              const float* __restrict__ b1)
{
    __shared__ float xs[64 * XS_STRIDE];
    __shared__ float ws[32 * HID];

    const int tid = threadIdx.x;
    const int bs  = blockIdx.x * 64;
    const int c   = tid & 7;
    const int r   = tid >> 3;

    const int xf0_s = tid >> 3,         xf0_k = (tid & 7) * 4;
    const int xf1_s = (256 + tid) >> 3, xf1_k = ((256 + tid) & 7) * 4;

    float4 px0, px1, pw[4];

    px0 = *(const float4*)&x[(bs + xf0_s) * IN_DIM + xf0_k];
    px1 = *(const float4*)&x[(bs + xf1_s) * IN_DIM + xf1_k];
#pragma unroll
    for (int i = 0; i < 4; i++) {
        int f  = i * 256 + tid;
        int kk = f >> 5;
        int h4 = (f & 31) * 4;
        pw[i] = *(const float4*)&g_W1T[kk * HID + h4];
    }

    float acc[4][8];
#pragma unroll
    for (int i = 0; i < 4; i++)
#pragma unroll
        for (int j = 0; j < 8; j++) acc[i][j] = 0.0f;

    for (int ch = 0; ch < IN_DIM / 32; ch++) {
        *(float4*)&xs[xf0_s * XS_STRIDE + xf0_k] = px0;
        *(float4*)&xs[xf1_s * XS_STRIDE + xf1_k] = px1;
#pragma unroll
        for (int i = 0; i < 4; i++) {
            int f  = i * 256 + tid;
            int kk = f >> 5;
            int h4 = (f & 31) * 4;
            *(float4*)&ws[kk * HID + h4] = pw[i];
        }
        __syncthreads();

        if (ch + 1 < IN_DIM / 32) {
            int kc = (ch + 1) * 32;
            px0 = *(const float4*)&x[(bs + xf0_s) * IN_DIM + kc + xf0_k];
            px1 = *(const float4*)&x[(bs + xf1_s) * IN_DIM + kc + xf1_k];
#pragma unroll
            for (int i = 0; i < 4; i++) {
                int f  = i * 256 + tid;
                int kk = f >> 5;
                int h4 = (f & 31) * 4;
                pw[i] = *(const float4*)&g_W1T[(kc + kk) * HID + h4];
            }
        }

#pragma unroll
        for (int k = 0; k < 32; k += 4) {
            float4 xv[8];
#pragma unroll
            for (int j = 0; j < 8; j++)
                xv[j] = *(const float4*)&xs[(c + 8 * j) * XS_STRIDE + k];
            float4 wv[4];
#pragma unroll
            for (int kk = 0; kk < 4; kk++)
                wv[kk] = *(const float4*)&ws[(k + kk) * HID + r * 4];
#pragma unroll
            for (int kk = 0; kk < 4; kk++) {
                float w0 = wv[kk].x, w1 = wv[kk].y, w2 = wv[kk].z, w3 = wv[kk].w;
#pragma unroll
                for (int j = 0; j < 8; j++) {
                    float xvk = (kk == 0) ? xv[j].x : (kk == 1) ? xv[j].y
                              : (kk == 2) ? xv[j].z : xv[j].w;
                    acc[0][j] = fmaf(w0, xvk, acc[0][j]);
                    acc[1][j] = fmaf(w1, xvk, acc[1][j]);
                    acc[2][j] = fmaf(w2, xvk, acc[2][j]);
                    acc[3][j] = fmaf(w3, xvk, acc[3][j]);
                }
            }
        }
        __syncthreads();
    }

    float4 b1v = *(const float4*)&b1[r * 4];
#pragma unroll
    for (int j = 0; j < 8; j++) {
        int s = bs + c + 8 * j;
        float4 o;
        o.x = acc[0][j] + b1v.x;
        o.y = acc[1][j] + b1v.y;
        o.z = acc[2][j] + b1v.z;
        o.w = acc[3][j] + b1v.w;
        *(float4*)&g_cur1[s * HID + r * 4] = o;
    }
}

// ---------------------------------------------------------------------------
// K2: layer-1 LIF recurrence + spike mask packing (ballot).
// ---------------------------------------------------------------------------
__global__ __launch_bounds__(256) void k2_lif1()
{
    __shared__ uint32_t sm[T_STEPS][8][4];

    const int tid  = threadIdx.x;
    const int w    = tid >> 5;
    const int lane = tid & 31;
    const int g    = w & 3;
    const int q    = w >> 2;
    const int sb   = blockIdx.x * 8 + q * 4;
    const int h    = g * 32 + lane;

    float cur[4], mem[4];
#pragma unroll
    for (int j = 0; j < 4; j++) {
        cur[j] = g_cur1[(sb + j) * HID + h];
        mem[j] = 0.0f;
    }

    for (int t = 0; t < T_STEPS; t++) {
#pragma unroll
        for (int j = 0; j < 4; j++) {
            float m  = mem[j];
            float rf = (m > 1.0f) ? 1.0f : 0.0f;
            m = fmaf(BETA, m, cur[j]) - rf;
            mem[j] = m;
            unsigned bal = __ballot_sync(0xffffffffu, m > 1.0f);
            if (lane == 0) sm[t][q * 4 + j][g] = bal;
        }
    }
    __syncthreads();

    for (int idx = tid; idx < T_STEPS * 8; idx += 256) {
        int t  = idx >> 3;
        int sl = idx & 7;
        g_masks[t * BN + blockIdx.x * 8 + sl] = *(const uint4*)&sm[t][sl][0];
    }
}

// ---------------------------------------------------------------------------
// K3a: materialize cur2[half][t][s] = LUT-sum(masks[t][s]) + b2[half].
// Fully parallel over (s, t, half). CTA = 256 samples x 4 timesteps x 1 half.
// LUT[16][256][4] = 64 KB dyn smem (3 CTAs/SM). grid = 64 * 16 * 2 = 2048.
// ---------------------------------------------------------------------------
static __device__ __forceinline__ float4 f4add(float4 a, float4 b)
{
    return make_float4(a.x + b.x, a.y + b.y, a.z + b.z, a.w + b.w);
}

__global__ __launch_bounds__(256) void k3a_cur2(const float* __restrict__ W2,
                                                const float* __restrict__ b2)
{
    extern __shared__ float lut[];   // [16][256][4]
    const int tid  = threadIdx.x;
    const unsigned b = blockIdx.x;
    const int half = b & 1;
    const int tb   = (b >> 1) & 15;       // timestep block (4 t's)
    const int sb   = (b >> 5) * 256;      // sample base

    // Build LUT: thread owns 16 bytes of one chunk; W2 rows cached in regs.
    {
        const int chunk = tid >> 4;           // 0..15
        const int bbase = (tid & 15) * 16;
        float w[4][8];
#pragma unroll
        for (int cc = 0; cc < 4; cc++)
#pragma unroll
            for (int j = 0; j < 8; j++)
                w[cc][j] = W2[(half * 4 + cc) * HID + chunk * 8 + j];

        for (int i = 0; i < 16; i++) {
            int byt = bbase + i;
            float4 v = make_float4(0.f, 0.f, 0.f, 0.f);
#pragma unroll
            for (int j = 0; j < 8; j++) {
                if ((byt >> j) & 1) {
                    v.x += w[0][j]; v.y += w[1][j];
                    v.z += w[2][j]; v.w += w[3][j];
                }
            }
            *(float4*)&lut[(chunk * 256 + byt) * 4] = v;
        }
    }
    __syncthreads();

    const int s = sb + tid;
    float4 b2v = make_float4(b2[half * 4 + 0], b2[half * 4 + 1],
                             b2[half * 4 + 2], b2[half * 4 + 3]);

    uint4 m[4];
#pragma unroll
    for (int i = 0; i < 4; i++)
        m[i] = g_masks[(tb * 4 + i) * BN + s];

#pragma unroll
    for (int i = 0; i < 4; i++) {
        uint32_t w[4] = {m[i].x, m[i].y, m[i].z, m[i].w};
        float4 sg[4];
#pragma unroll
        for (int g = 0; g < 4; g++) {
            const float* lg = &lut[g * 4096];
            uint32_t wg = w[g];
            float4 q0 = *(const float4*)&lg[           ((wg        & 255u) << 2)];
            float4 q1 = *(const float4*)&lg[1 * 1024 + (((wg >> 8)  & 255u) << 2)];
            float4 q2 = *(const float4*)&lg[2 * 1024 + (((wg >> 16) & 255u) << 2)];
            float4 q3 = *(const float4*)&lg[3 * 1024 + ((wg >> 24)         << 2)];
            sg[g] = f4add(f4add(q0, q1), f4add(q2, q3));
        }
        float4 cur = f4add(f4add(f4add(sg[0], sg[1]), f4add(sg[2], sg[3])), b2v);
        g_cur2[half][(tb * 4 + i) * BN + s] = cur;
    }
}

// ---------------------------------------------------------------------------
// K3b: LIF-2 scan over t. Thread = (sample, class-half). Coalesced float4
// loads from [t][s] planes. grid = 2*BN/128 = 256 CTAs x 128 threads.
// ---------------------------------------------------------------------------
__global__ __launch_bounds__(128) void k3b_scan(float* __restrict__ out)
{
    const int u    = blockIdx.x * 128 + threadIdx.x;
    const int s    = u & (BN - 1);
    const int half = u >> 14;

    const float4* __restrict__ cp = &g_cur2[half][s];

    float4 mem = make_float4(0.f, 0.f, 0.f, 0.f);
    float4 acc = mem, rst = mem;

    float4 nxt = cp[0];
#pragma unroll 4
    for (int t = 0; t < T_STEPS; t++) {
        float4 cur = nxt;
        if (t + 1 < T_STEPS) nxt = cp[(size_t)(t + 1) * BN];

        mem.x = fmaf(BETA, mem.x, cur.x) - rst.x;
        mem.y = fmaf(BETA, mem.y, cur.y) - rst.y;
        mem.z = fmaf(BETA, mem.z, cur.z) - rst.z;
        mem.w = fmaf(BETA, mem.w, cur.w) - rst.w;
        rst.x = (mem.x > 1.0f) ? 1.0f : 0.0f;
        rst.y = (mem.y > 1.0f) ? 1.0f : 0.0f;
        rst.z = (mem.z > 1.0f) ? 1.0f : 0.0f;
        rst.w = (mem.w > 1.0f) ? 1.0f : 0.0f;
        acc.x += rst.x; acc.y += rst.y; acc.z += rst.z; acc.w += rst.w;
    }

    *(float4*)&out[s * 8 + half * 4] = acc;
}

// ---------------------------------------------------------------------------
extern "C" void kernel_launch(void* const* d_in, const int* in_sizes, int n_in,
                              void* d_out, int out_size)
{
    const float* x  = (const float*)d_in[0];
    const float* W1 = (const float*)d_in[1];
    const float* b1 = (const float*)d_in[2];
    const float* W2 = (const float*)d_in[3];
    const float* b2 = (const float*)d_in[4];
    float* out = (float*)d_out;

    k0_w1t<<<(IN_DIM * HID) / 256, 256>>>(W1);
    k1_fc1<<<BN / 64, 256>>>(x, b1);
    k2_lif1<<<BN / 8, 256>>>();

    cudaFuncSetAttribute(k3a_cur2, cudaFuncAttributeMaxDynamicSharedMemorySize, 65536);
    k3a_cur2<<<(BN / 256) * (T_STEPS / 4) * 2, 256, 65536>>>(W2, b2);
    k3b_scan<<<2 * BN / 128, 128>>>(out);
}

// round 7
// speedup vs baseline: 1.1584x; 1.1584x over previous
#include <cuda_runtime.h>
#include <stdint.h>

#define BN      16384
#define IN_DIM  256
#define HID     128
#define NCLS    8
#define T_STEPS 64
#define BETA    0.9f

// Scratch (no cudaMalloc allowed)
__device__ float g_cur1[BN * HID];          // 8 MB
__device__ uint4 g_masks[T_STEPS * BN];     // 16 MB  [t][s] spike masks
__device__ float g_W1T[IN_DIM * HID];       // 128 KB W1 transposed: [k][h]

// ---------------------------------------------------------------------------
// K0: W1T[k][h] = W1[h][k]
// ---------------------------------------------------------------------------
__global__ __launch_bounds__(256) void k0_w1t(const float* __restrict__ W1)
{
    int idx = blockIdx.x * 256 + threadIdx.x;
    int h = idx & (HID - 1);
    int k = idx >> 7;
    g_W1T[k * HID + h] = W1[h * IN_DIM + k];
}

// ---------------------------------------------------------------------------
// K1: cur1 = x @ W1^T + b1.  (EXACT R5 version — bitwise-stable ordering:
// single fp32 accumulator per output, k ascending 0..255.)
// CTA tile: 64 samples x 128 hid. K chunks of 32. 256 thr, 8s x 4h/thread.
// ---------------------------------------------------------------------------
#define XS_STRIDE 36

__global__ __launch_bounds__(256) void k1_fc1(const float* __restrict__ x,
                                              const float* __restrict__ b1)
{
    __shared__ float xs[64 * XS_STRIDE];
    __shared__ float ws[32 * HID];

    const int tid = threadIdx.x;
    const int bs  = blockIdx.x * 64;
    const int c   = tid & 7;
    const int r   = tid >> 3;

    const int xf0_s = tid >> 3,         xf0_k = (tid & 7) * 4;
    const int xf1_s = (256 + tid) >> 3, xf1_k = ((256 + tid) & 7) * 4;

    float4 px0, px1, pw[4];

    px0 = *(const float4*)&x[(bs + xf0_s) * IN_DIM + xf0_k];
    px1 = *(const float4*)&x[(bs + xf1_s) * IN_DIM + xf1_k];
#pragma unroll
    for (int i = 0; i < 4; i++) {
        int f  = i * 256 + tid;
        int kk = f >> 5;
        int h4 = (f & 31) * 4;
        pw[i] = *(const float4*)&g_W1T[kk * HID + h4];
    }

    float acc[4][8];
#pragma unroll
    for (int i = 0; i < 4; i++)
#pragma unroll
        for (int j = 0; j < 8; j++) acc[i][j] = 0.0f;

    for (int ch = 0; ch < IN_DIM / 32; ch++) {
        *(float4*)&xs[xf0_s * XS_STRIDE + xf0_k] = px0;
        *(float4*)&xs[xf1_s * XS_STRIDE + xf1_k] = px1;
#pragma unroll
        for (int i = 0; i < 4; i++) {
            int f  = i * 256 + tid;
            int kk = f >> 5;
            int h4 = (f & 31) * 4;
            *(float4*)&ws[kk * HID + h4] = pw[i];
        }
        __syncthreads();

        if (ch + 1 < IN_DIM / 32) {
            int kc = (ch + 1) * 32;
            px0 = *(const float4*)&x[(bs + xf0_s) * IN_DIM + kc + xf0_k];
            px1 = *(const float4*)&x[(bs + xf1_s) * IN_DIM + kc + xf1_k];
#pragma unroll
            for (int i = 0; i < 4; i++) {
                int f  = i * 256 + tid;
                int kk = f >> 5;
                int h4 = (f & 31) * 4;
                pw[i] = *(const float4*)&g_W1T[(kc + kk) * HID + h4];
            }
        }

#pragma unroll
        for (int k = 0; k < 32; k += 4) {
            float4 xv[8];
#pragma unroll
            for (int j = 0; j < 8; j++)
                xv[j] = *(const float4*)&xs[(c + 8 * j) * XS_STRIDE + k];
            float4 wv[4];
#pragma unroll
            for (int kk = 0; kk < 4; kk++)
                wv[kk] = *(const float4*)&ws[(k + kk) * HID + r * 4];
#pragma unroll
            for (int kk = 0; kk < 4; kk++) {
                float w0 = wv[kk].x, w1 = wv[kk].y, w2 = wv[kk].z, w3 = wv[kk].w;
#pragma unroll
                for (int j = 0; j < 8; j++) {
                    float xvk = (kk == 0) ? xv[j].x : (kk == 1) ? xv[j].y
                              : (kk == 2) ? xv[j].z : xv[j].w;
                    acc[0][j] = fmaf(w0, xvk, acc[0][j]);
                    acc[1][j] = fmaf(w1, xvk, acc[1][j]);
                    acc[2][j] = fmaf(w2, xvk, acc[2][j]);
                    acc[3][j] = fmaf(w3, xvk, acc[3][j]);
                }
            }
        }
        __syncthreads();
    }

    float4 b1v = *(const float4*)&b1[r * 4];
#pragma unroll
    for (int j = 0; j < 8; j++) {
        int s = bs + c + 8 * j;
        float4 o;
        o.x = acc[0][j] + b1v.x;
        o.y = acc[1][j] + b1v.y;
        o.z = acc[2][j] + b1v.z;
        o.w = acc[3][j] + b1v.w;
        *(float4*)&g_cur1[s * HID + r * 4] = o;
    }
}

// ---------------------------------------------------------------------------
// K2: layer-1 LIF recurrence + spike mask packing (ballot).
// ---------------------------------------------------------------------------
__global__ __launch_bounds__(256) void k2_lif1()
{
    __shared__ uint32_t sm[T_STEPS][8][4];

    const int tid  = threadIdx.x;
    const int w    = tid >> 5;
    const int lane = tid & 31;
    const int g    = w & 3;
    const int q    = w >> 2;
    const int sb   = blockIdx.x * 8 + q * 4;
    const int h    = g * 32 + lane;

    float cur[4], mem[4];
#pragma unroll
    for (int j = 0; j < 4; j++) {
        cur[j] = g_cur1[(sb + j) * HID + h];
        mem[j] = 0.0f;
    }

    for (int t = 0; t < T_STEPS; t++) {
#pragma unroll
        for (int j = 0; j < 4; j++) {
            float m  = mem[j];
            float rf = (m > 1.0f) ? 1.0f : 0.0f;
            m = fmaf(BETA, m, cur[j]) - rf;
            mem[j] = m;
            unsigned bal = __ballot_sync(0xffffffffu, m > 1.0f);
            if (lane == 0) sm[t][q * 4 + j][g] = bal;
        }
    }
    __syncthreads();

    for (int idx = tid; idx < T_STEPS * 8; idx += 256) {
        int t  = idx >> 3;
        int sl = idx & 7;
        g_masks[t * BN + blockIdx.x * 8 + sl] = *(const uint4*)&sm[t][sl][0];
    }
}

// ---------------------------------------------------------------------------
// K3: fused layer-2 LUT + LIF scan, class-PAIR split for occupancy.
// CTA = (128-sample block) x (class pair p: classes 2p, 2p+1).
// LUT[16][256][2] = 32 KB dyn smem -> ~3.5 CTAs/SM, ~14 warps/SM.
// Math bitwise-identical per class to the R4 kernel (rel_err 0.0).
// ---------------------------------------------------------------------------
__global__ __launch_bounds__(128) void k3_lif2(const float* __restrict__ W2,
                                               const float* __restrict__ b2,
                                               float* __restrict__ out)
{
    extern __shared__ float lut[];   // [16][256][2]
    const int tid  = threadIdx.x;
    const int pair = blockIdx.x & 3;
    const int s    = (blockIdx.x >> 2) * 128 + tid;

    {
        const int chunk = tid >> 3;            // 0..15
        const int bbase = (tid & 7) * 32;
        float w0[8], w1[8];
#pragma unroll
        for (int j = 0; j < 8; j++) {
            w0[j] = W2[(2 * pair + 0) * HID + chunk * 8 + j];
            w1[j] = W2[(2 * pair + 1) * HID + chunk * 8 + j];
        }
        for (int i = 0; i < 32; i++) {
            int byt = bbase + i;
            float v0 = 0.f, v1 = 0.f;
#pragma unroll
            for (int j = 0; j < 8; j++) {
                if ((byt >> j) & 1) { v0 += w0[j]; v1 += w1[j]; }
            }
            *(float2*)&lut[(chunk * 256 + byt) * 2] = make_float2(v0, v1);
        }
    }
    __syncthreads();

    const float2 b2v = make_float2(b2[2 * pair], b2[2 * pair + 1]);
    const uint4* mp = &g_masks[s];

    uint4 m0 = mp[0];
    uint4 m1 = mp[BN];

    float mA = 0.f, mB = 0.f, aA = 0.f, aB = 0.f, rA = 0.f, rB = 0.f;

    for (int t = 0; t < T_STEPS; t++) {
        uint4 m = m0;
        m0 = m1;
        if (t + 2 < T_STEPS) m1 = mp[(size_t)(t + 2) * BN];

        uint32_t w[4] = {m.x, m.y, m.z, m.w};
        float2 sg[4];
#pragma unroll
        for (int g = 0; g < 4; g++) {
            const float* lg = &lut[g * 2048];
            uint32_t wg = w[g];
            float2 q0 = *(const float2*)&lg[           ((wg        & 255u) << 1)];
            float2 q1 = *(const float2*)&lg[1 * 512 + (((wg >> 8)  & 255u) << 1)];
            float2 q2 = *(const float2*)&lg[2 * 512 + (((wg >> 16) & 255u) << 1)];
            float2 q3 = *(const float2*)&lg[3 * 512 + ((wg >> 24)         << 1)];
            sg[g] = make_float2((q0.x + q1.x) + (q2.x + q3.x),
                                (q0.y + q1.y) + (q2.y + q3.y));
        }
        float curA = ((sg[0].x + sg[1].x) + (sg[2].x + sg[3].x)) + b2v.x;
        float curB = ((sg[0].y + sg[1].y) + (sg[2].y + sg[3].y)) + b2v.y;

        mA = fmaf(BETA, mA, curA) - rA;
        mB = fmaf(BETA, mB, curB) - rB;
        rA = (mA > 1.0f) ? 1.0f : 0.0f;
        rB = (mB > 1.0f) ? 1.0f : 0.0f;
        aA += rA;
        aB += rB;
    }

    *(float2*)&out[s * 8 + 2 * pair] = make_float2(aA, aB);
}

// ---------------------------------------------------------------------------
extern "C" void kernel_launch(void* const* d_in, const int* in_sizes, int n_in,
                              void* d_out, int out_size)
{
    const float* x  = (const float*)d_in[0];
    const float* W1 = (const float*)d_in[1];
    const float* b1 = (const float*)d_in[2];
    const float* W2 = (const float*)d_in[3];
    const float* b2 = (const float*)d_in[4];
    float* out = (float*)d_out;

    k0_w1t<<<(IN_DIM * HID) / 256, 256>>>(W1);
    k1_fc1<<<BN / 64, 256>>>(x, b1);
    k2_lif1<<<BN / 8, 256>>>();

    cudaFuncSetAttribute(k3_lif2, cudaFuncAttributeMaxDynamicSharedMemorySize, 32768);
    k3_lif2<<<(BN / 128) * 4, 128, 32768>>>(W2, b2, out);
}